// round 1
// baseline (speedup 1.0000x reference)
#include <cuda_runtime.h>
#include <math.h>

#define D_MODEL 1024
#define SEQ     2048
#define BATCH   2
#define NH      16
#define HD      64
#define MTOT    (BATCH*SEQ)   // 4096

// ---------------- scratch (no allocations allowed) ----------------
__device__ float g_q[MTOT*D_MODEL];
__device__ float g_k[MTOT*D_MODEL];
__device__ float g_v[MTOT*D_MODEL];
__device__ float g_attn[MTOT*D_MODEL];

// ---------------- SGEMM: C[M,N] = A[M,K] @ B[K,N], row-major ----------------
#define BM 128
#define BN 128
#define BK 16
#define TM 8
#define TN 8

__global__ __launch_bounds__(256, 2) void sgemm_kernel(
    const float* __restrict__ A, const float* __restrict__ B,
    float* __restrict__ C, int M, int N, int K)
{
    __shared__ float As[BK][BM + 4];   // A stored transposed: As[k][m]
    __shared__ float Bs[BK][BN];

    const int tid = threadIdx.x;
    const int tx = tid & 15;           // 0..15
    const int ty = tid >> 4;           // 0..15
    const int rowbase = blockIdx.y * BM;
    const int colbase = blockIdx.x * BN;

    float acc[TM][TN];
    #pragma unroll
    for (int i = 0; i < TM; i++)
        #pragma unroll
        for (int j = 0; j < TN; j++) acc[i][j] = 0.f;

    for (int kb = 0; kb < K; kb += BK) {
        // load A tile (BM x BK), store transposed
        #pragma unroll
        for (int l = 0; l < 2; l++) {
            int e   = tid + l * 256;       // 0..511
            int ar  = e >> 2;              // 0..127
            int ac4 = e & 3;               // 0..3
            float4 v = *(const float4*)(A + (size_t)(rowbase + ar) * K + kb + ac4 * 4);
            As[ac4*4 + 0][ar] = v.x;
            As[ac4*4 + 1][ar] = v.y;
            As[ac4*4 + 2][ar] = v.z;
            As[ac4*4 + 3][ar] = v.w;
        }
        // load B tile (BK x BN)
        #pragma unroll
        for (int l = 0; l < 2; l++) {
            int e   = tid + l * 256;
            int br  = e >> 5;              // 0..15
            int bc4 = e & 31;              // 0..31
            *(float4*)(&Bs[br][bc4*4]) =
                *(const float4*)(B + (size_t)(kb + br) * N + colbase + bc4 * 4);
        }
        __syncthreads();

        #pragma unroll
        for (int kk = 0; kk < BK; kk++) {
            float a[TM], b[TN];
            *(float4*)&a[0] = *(const float4*)&As[kk][ty*TM];
            *(float4*)&a[4] = *(const float4*)&As[kk][ty*TM + 4];
            *(float4*)&b[0] = *(const float4*)&Bs[kk][tx*TN];
            *(float4*)&b[4] = *(const float4*)&Bs[kk][tx*TN + 4];
            #pragma unroll
            for (int i = 0; i < TM; i++)
                #pragma unroll
                for (int j = 0; j < TN; j++)
                    acc[i][j] = fmaf(a[i], b[j], acc[i][j]);
        }
        __syncthreads();
    }

    #pragma unroll
    for (int i = 0; i < TM; i++) {
        float* cp = C + (size_t)(rowbase + ty*TM + i) * N + colbase + tx*TN;
        *(float4*)(cp)     = make_float4(acc[i][0], acc[i][1], acc[i][2], acc[i][3]);
        *(float4*)(cp + 4) = make_float4(acc[i][4], acc[i][5], acc[i][6], acc[i][7]);
    }
}

// ---------------- Flash attention, 64-row Q tiles ----------------
// smem tiles padded to stride 68 (keeps 16B alignment, kills 64-stride conflicts)
#define TPAD 68
#define ATT_SMEM ((4*64*TPAD + 3*64) * (int)sizeof(float))
#define SOFTMAX_SCALE 0.125f   // 1/sqrt(64)

__global__ __launch_bounds__(256, 1) void attn_kernel(
    const float* __restrict__ Q, const float* __restrict__ Kg,
    const float* __restrict__ Vg, float* __restrict__ O)
{
    extern __shared__ float smem[];
    float* sQt  = smem;                 // [64][TPAD]  sQt[d][r] = Q[r][d]
    float* sKt  = sQt + 64*TPAD;        // [64][TPAD]  sKt[d][c] = K[c][d]
    float* sV   = sKt + 64*TPAD;        // [64][TPAD]  sV[c][d]
    float* sPt  = sV  + 64*TPAD;        // [64][TPAD]  sPt[c][r]
    float* rowm = sPt + 64*TPAD;        // [64]
    float* rowl = rowm + 64;            // [64]
    float* rowa = rowl + 64;            // [64]

    const int tid = threadIdx.x;
    const int tx  = tid & 15;           // col group
    const int ty  = tid >> 4;           // row group
    const int b   = blockIdx.z;
    const int h   = blockIdx.y;
    const int qbase = blockIdx.x * 64;
    const size_t bh_off = ((size_t)b * SEQ) * D_MODEL + (size_t)h * HD;

    // load Q tile transposed
    #pragma unroll
    for (int l = 0; l < 4; l++) {
        int e  = tid + l * 256;         // 0..1023
        int r  = e >> 4;                // 0..63
        int d4 = e & 15;                // 0..15
        float4 v = *(const float4*)(Q + bh_off + (size_t)(qbase + r) * D_MODEL + d4 * 4);
        sQt[(d4*4 + 0)*TPAD + r] = v.x;
        sQt[(d4*4 + 1)*TPAD + r] = v.y;
        sQt[(d4*4 + 2)*TPAD + r] = v.z;
        sQt[(d4*4 + 3)*TPAD + r] = v.w;
    }
    if (tid < 64) { rowm[tid] = -INFINITY; rowl[tid] = 0.f; }

    float acc[4][4];
    #pragma unroll
    for (int i = 0; i < 4; i++)
        #pragma unroll
        for (int j = 0; j < 4; j++) acc[i][j] = 0.f;

    for (int kt = 0; kt < SEQ / 64; kt++) {
        const int kbase = kt * 64;
        // load K (transposed) and V tiles
        #pragma unroll
        for (int l = 0; l < 4; l++) {
            int e  = tid + l * 256;
            int c  = e >> 4;
            int d4 = e & 15;
            float4 kv = *(const float4*)(Kg + bh_off + (size_t)(kbase + c) * D_MODEL + d4 * 4);
            sKt[(d4*4 + 0)*TPAD + c] = kv.x;
            sKt[(d4*4 + 1)*TPAD + c] = kv.y;
            sKt[(d4*4 + 2)*TPAD + c] = kv.z;
            sKt[(d4*4 + 3)*TPAD + c] = kv.w;
            float4 vv = *(const float4*)(Vg + bh_off + (size_t)(kbase + c) * D_MODEL + d4 * 4);
            *(float4*)(&sV[c*TPAD + d4*4]) = vv;
        }
        __syncthreads();

        // S = Q K^T * scale  (4x4 per thread)
        float s[4][4];
        #pragma unroll
        for (int i = 0; i < 4; i++)
            #pragma unroll
            for (int j = 0; j < 4; j++) s[i][j] = 0.f;

        #pragma unroll 8
        for (int d = 0; d < HD; d++) {
            float qa[4], kb2[4];
            *(float4*)qa  = *(const float4*)&sQt[d*TPAD + ty*4];
            *(float4*)kb2 = *(const float4*)&sKt[d*TPAD + tx*4];
            #pragma unroll
            for (int i = 0; i < 4; i++)
                #pragma unroll
                for (int j = 0; j < 4; j++)
                    s[i][j] = fmaf(qa[i], kb2[j], s[i][j]);
        }
        // write P^T (scaled)
        #pragma unroll
        for (int j = 0; j < 4; j++) {
            float4 p = make_float4(s[0][j]*SOFTMAX_SCALE, s[1][j]*SOFTMAX_SCALE,
                                   s[2][j]*SOFTMAX_SCALE, s[3][j]*SOFTMAX_SCALE);
            *(float4*)(&sPt[(tx*4 + j)*TPAD + ty*4]) = p;
        }
        __syncthreads();

        // online softmax per row (64 threads, coalesced across r)
        if (tid < 64) {
            const int r = tid;
            float tm = -INFINITY;
            #pragma unroll 8
            for (int c = 0; c < 64; c++) tm = fmaxf(tm, sPt[c*TPAD + r]);
            const float mo = rowm[r];
            const float mn = fmaxf(mo, tm);
            const float al = __expf(mo - mn);
            float sum = 0.f;
            #pragma unroll 8
            for (int c = 0; c < 64; c++) {
                float p = __expf(sPt[c*TPAD + r] - mn);
                sPt[c*TPAD + r] = p;
                sum += p;
            }
            rowl[r] = rowl[r] * al + sum;
            rowm[r] = mn;
            rowa[r] = al;
        }
        __syncthreads();

        // O = O*alpha + P V
        float al_i[4];
        *(float4*)al_i = *(const float4*)&rowa[ty*4];
        #pragma unroll
        for (int i = 0; i < 4; i++)
            #pragma unroll
            for (int j = 0; j < 4; j++) acc[i][j] *= al_i[i];

        #pragma unroll 8
        for (int c = 0; c < 64; c++) {
            float p[4], vv[4];
            *(float4*)p  = *(const float4*)&sPt[c*TPAD + ty*4];
            *(float4*)vv = *(const float4*)&sV [c*TPAD + tx*4];
            #pragma unroll
            for (int i = 0; i < 4; i++)
                #pragma unroll
                for (int j = 0; j < 4; j++)
                    acc[i][j] = fmaf(p[i], vv[j], acc[i][j]);
        }
        __syncthreads();
    }

    // normalize and store
    float linv[4];
    #pragma unroll
    for (int i = 0; i < 4; i++) linv[i] = 1.f / rowl[ty*4 + i];
    #pragma unroll
    for (int i = 0; i < 4; i++) {
        float4 o = make_float4(acc[i][0]*linv[i], acc[i][1]*linv[i],
                               acc[i][2]*linv[i], acc[i][3]*linv[i]);
        *(float4*)(O + bh_off + (size_t)(qbase + ty*4 + i) * D_MODEL + tx*4) = o;
    }
}

// ---------------- launch ----------------
extern "C" void kernel_launch(void* const* d_in, const int* in_sizes, int n_in,
                              void* d_out, int out_size)
{
    const float* x  = (const float*)d_in[0];
    const float* Wq = (const float*)d_in[1];
    const float* Wk = (const float*)d_in[2];
    const float* Wv = (const float*)d_in[3];
    const float* Wo = (const float*)d_in[4];
    float* out = (float*)d_out;

    float *q, *k, *v, *attn;
    cudaGetSymbolAddress((void**)&q,    g_q);
    cudaGetSymbolAddress((void**)&k,    g_k);
    cudaGetSymbolAddress((void**)&v,    g_v);
    cudaGetSymbolAddress((void**)&attn, g_attn);

    cudaFuncSetAttribute(attn_kernel,
                         cudaFuncAttributeMaxDynamicSharedMemorySize, ATT_SMEM);

    dim3 gg(D_MODEL / BN, MTOT / BM);   // (8, 32)
    sgemm_kernel<<<gg, 256>>>(x, Wq, q, MTOT, D_MODEL, D_MODEL);
    sgemm_kernel<<<gg, 256>>>(x, Wk, k, MTOT, D_MODEL, D_MODEL);
    sgemm_kernel<<<gg, 256>>>(x, Wv, v, MTOT, D_MODEL, D_MODEL);

    attn_kernel<<<dim3(SEQ/64, NH, BATCH), 256, ATT_SMEM>>>(q, k, v, attn);

    sgemm_kernel<<<gg, 256>>>(attn, Wo, out, MTOT, D_MODEL, D_MODEL);
}

// round 5
// speedup vs baseline: 1.3782x; 1.3782x over previous
#include <cuda_runtime.h>
#include <math.h>
#include <stdint.h>

#define D_MODEL 1024
#define SEQ     2048
#define BATCH   2
#define NH      16
#define HD      64
#define MTOT    (BATCH*SEQ)   // 4096

// ---------------- scratch (no allocations allowed) ----------------
__device__ float g_q[MTOT*D_MODEL];
__device__ float g_k[MTOT*D_MODEL];
__device__ float g_v[MTOT*D_MODEL];
__device__ float g_attn[MTOT*D_MODEL];
__device__ float g_wt[4*D_MODEL*D_MODEL];   // transposed weights (N x K, K-major)

// single dynamic smem symbol (attention only)
extern __shared__ char dynsmem[];

// ==================== mma.sync tf32 GEMM ====================
// C[M,N] = A[M,K] @ Bt[N,K]^T  (both K-major). CTA tile 128x128, BK=32.
// 8 warps arranged 2(M) x 4(N); warp tile 64x32 = 4x4 grid of m16n8k8 mma.

__device__ __forceinline__ int swz(int r, int c) {
    // SW128-style xor swizzle on 16B granularity, 128B rows (32 words)
    return r * 32 + ((((c >> 2) ^ r) & 7) << 2) + (c & 3);
}

__device__ __forceinline__ uint4 tf32x4(float4 v) {
    uint4 u;
    asm("cvt.rna.tf32.f32 %0, %1;" : "=r"(u.x) : "f"(v.x));
    asm("cvt.rna.tf32.f32 %0, %1;" : "=r"(u.y) : "f"(v.y));
    asm("cvt.rna.tf32.f32 %0, %1;" : "=r"(u.z) : "f"(v.z));
    asm("cvt.rna.tf32.f32 %0, %1;" : "=r"(u.w) : "f"(v.w));
    return u;
}

#define MMA_TF32(c, a, b) \
    asm volatile("mma.sync.aligned.m16n8k8.row.col.f32.tf32.tf32.f32 " \
        "{%0,%1,%2,%3}, {%4,%5,%6,%7}, {%8,%9}, {%0,%1,%2,%3};" \
        : "+f"((c)[0]), "+f"((c)[1]), "+f"((c)[2]), "+f"((c)[3]) \
        : "r"((a)[0]), "r"((a)[1]), "r"((a)[2]), "r"((a)[3]), \
          "r"((b)[0]), "r"((b)[1]))

__global__ __launch_bounds__(256, 1) void gemm_mma_kernel(
    const float* __restrict__ A,
    const float* __restrict__ B0, const float* __restrict__ B1, const float* __restrict__ B2,
    float* __restrict__ C0, float* __restrict__ C1, float* __restrict__ C2)
{
    __shared__ float sA[128 * 32];
    __shared__ float sB[128 * 32];

    const int tid    = threadIdx.x;
    const int wid    = tid >> 5;
    const int lane   = tid & 31;
    const int warp_m = wid & 1;       // 0..1
    const int warp_n = wid >> 1;      // 0..3
    const int g      = lane >> 2;     // group id 0..7
    const int tg     = lane & 3;      // thread-in-group 0..3

    const int z = blockIdx.z;
    const float* __restrict__ B = (z == 0) ? B0 : ((z == 1) ? B1 : B2);
    float* __restrict__ C       = (z == 0) ? C0 : ((z == 1) ? C1 : C2);
    const int colbase = blockIdx.x * 128;
    const int rowbase = blockIdx.y * 128;

    float acc[4][4][4];
    #pragma unroll
    for (int mi = 0; mi < 4; mi++)
        #pragma unroll
        for (int ni = 0; ni < 4; ni++)
            #pragma unroll
            for (int q = 0; q < 4; q++) acc[mi][ni][q] = 0.f;

    // preload tile 0 into regs
    float4 pa[4], pb[4];
    #pragma unroll
    for (int l = 0; l < 4; l++) {
        int e = tid + l * 256;        // 0..1023
        int r = e >> 3, c4 = e & 7;
        pa[l] = *(const float4*)(A + (size_t)(rowbase + r) * D_MODEL + c4 * 4);
        pb[l] = *(const float4*)(B + (size_t)(colbase + r) * D_MODEL + c4 * 4);
    }

    const int NK = D_MODEL / 32;      // 32
    for (int kt = 0; kt < NK; kt++) {
        __syncthreads();              // previous compute done before overwrite
        #pragma unroll
        for (int l = 0; l < 4; l++) {
            int e = tid + l * 256;
            int r = e >> 3, c4 = e & 7;
            *(uint4*)&sA[swz(r, c4 * 4)] = tf32x4(pa[l]);
            *(uint4*)&sB[swz(r, c4 * 4)] = tf32x4(pb[l]);
        }
        __syncthreads();

        if (kt < NK - 1) {            // prefetch next tile (overlaps compute)
            const float* An = A + (kt + 1) * 32;
            const float* Bn = B + (kt + 1) * 32;
            #pragma unroll
            for (int l = 0; l < 4; l++) {
                int e = tid + l * 256;
                int r = e >> 3, c4 = e & 7;
                pa[l] = *(const float4*)(An + (size_t)(rowbase + r) * D_MODEL + c4 * 4);
                pb[l] = *(const float4*)(Bn + (size_t)(colbase + r) * D_MODEL + c4 * 4);
            }
        }

        #pragma unroll
        for (int kk = 0; kk < 4; kk++) {
            uint32_t af[4][4], bf[4][2];
            const int col = kk * 8 + tg;
            #pragma unroll
            for (int mi = 0; mi < 4; mi++) {
                int row = warp_m * 64 + mi * 16 + g;
                af[mi][0] = __float_as_uint(sA[swz(row,     col)]);
                af[mi][1] = __float_as_uint(sA[swz(row + 8, col)]);
                af[mi][2] = __float_as_uint(sA[swz(row,     col + 4)]);
                af[mi][3] = __float_as_uint(sA[swz(row + 8, col + 4)]);
            }
            #pragma unroll
            for (int ni = 0; ni < 4; ni++) {
                int n = warp_n * 32 + ni * 8 + g;
                bf[ni][0] = __float_as_uint(sB[swz(n, col)]);
                bf[ni][1] = __float_as_uint(sB[swz(n, col + 4)]);
            }
            #pragma unroll
            for (int mi = 0; mi < 4; mi++)
                #pragma unroll
                for (int ni = 0; ni < 4; ni++)
                    MMA_TF32(acc[mi][ni], af[mi], bf[ni]);
        }
    }

    // epilogue: c0,c1 at (row g, cols 2tg,2tg+1); c2,c3 at row g+8
    #pragma unroll
    for (int mi = 0; mi < 4; mi++) {
        int row = rowbase + warp_m * 64 + mi * 16 + g;
        #pragma unroll
        for (int ni = 0; ni < 4; ni++) {
            int col = colbase + warp_n * 32 + ni * 8 + tg * 2;
            *(float2*)(C + (size_t)row * D_MODEL + col) =
                make_float2(acc[mi][ni][0], acc[mi][ni][1]);
            *(float2*)(C + (size_t)(row + 8) * D_MODEL + col) =
                make_float2(acc[mi][ni][2], acc[mi][ni][3]);
        }
    }
}

// ==================== weight transpose: WT[n][k] = W[k][n] ====================
__global__ __launch_bounds__(256) void transpose_kernel(
    const float* __restrict__ s0, const float* __restrict__ s1,
    const float* __restrict__ s2, const float* __restrict__ s3,
    float* __restrict__ dst)
{
    __shared__ float ts[32][33];
    const int z = blockIdx.z;
    const float* src = (z == 0) ? s0 : (z == 1) ? s1 : (z == 2) ? s2 : s3;
    float* d = dst + (size_t)z * D_MODEL * D_MODEL;
    int x = blockIdx.x * 32 + threadIdx.x;
    int y = blockIdx.y * 32 + threadIdx.y;
    #pragma unroll
    for (int j = 0; j < 32; j += 8)
        ts[threadIdx.y + j][threadIdx.x] = src[(size_t)(y + j) * D_MODEL + x];
    __syncthreads();
    int x2 = blockIdx.y * 32 + threadIdx.x;
    int y2 = blockIdx.x * 32 + threadIdx.y;
    #pragma unroll
    for (int j = 0; j < 32; j += 8)
        d[(size_t)(y2 + j) * D_MODEL + x2] = ts[threadIdx.x][threadIdx.y + j];
}

// ==================== Flash attention (fp32) ====================
#define TPAD 68
#define ATT_SMEM ((4*64*TPAD + 3*64) * (int)sizeof(float))
#define SOFTMAX_SCALE 0.125f   // 1/sqrt(64)

__global__ __launch_bounds__(256, 1) void attn_kernel(
    const float* __restrict__ Q, const float* __restrict__ Kg,
    const float* __restrict__ Vg, float* __restrict__ O)
{
    float* smem = (float*)dynsmem;
    float* sQt  = smem;
    float* sKt  = sQt + 64*TPAD;
    float* sV   = sKt + 64*TPAD;
    float* sPt  = sV  + 64*TPAD;
    float* rowm = sPt + 64*TPAD;
    float* rowl = rowm + 64;
    float* rowa = rowl + 64;

    const int tid = threadIdx.x;
    const int tx  = tid & 15;
    const int ty  = tid >> 4;
    const int b   = blockIdx.z;
    const int h   = blockIdx.y;
    const int qbase = blockIdx.x * 64;
    const size_t bh_off = ((size_t)b * SEQ) * D_MODEL + (size_t)h * HD;

    #pragma unroll
    for (int l = 0; l < 4; l++) {
        int e  = tid + l * 256;
        int r  = e >> 4;
        int d4 = e & 15;
        float4 v = *(const float4*)(Q + bh_off + (size_t)(qbase + r) * D_MODEL + d4 * 4);
        sQt[(d4*4 + 0)*TPAD + r] = v.x;
        sQt[(d4*4 + 1)*TPAD + r] = v.y;
        sQt[(d4*4 + 2)*TPAD + r] = v.z;
        sQt[(d4*4 + 3)*TPAD + r] = v.w;
    }
    if (tid < 64) { rowm[tid] = -INFINITY; rowl[tid] = 0.f; }

    float acc[4][4];
    #pragma unroll
    for (int i = 0; i < 4; i++)
        #pragma unroll
        for (int j = 0; j < 4; j++) acc[i][j] = 0.f;

    for (int kt = 0; kt < SEQ / 64; kt++) {
        const int kbase = kt * 64;
        #pragma unroll
        for (int l = 0; l < 4; l++) {
            int e  = tid + l * 256;
            int c  = e >> 4;
            int d4 = e & 15;
            float4 kv = *(const float4*)(Kg + bh_off + (size_t)(kbase + c) * D_MODEL + d4 * 4);
            sKt[(d4*4 + 0)*TPAD + c] = kv.x;
            sKt[(d4*4 + 1)*TPAD + c] = kv.y;
            sKt[(d4*4 + 2)*TPAD + c] = kv.z;
            sKt[(d4*4 + 3)*TPAD + c] = kv.w;
            float4 vv = *(const float4*)(Vg + bh_off + (size_t)(kbase + c) * D_MODEL + d4 * 4);
            *(float4*)(&sV[c*TPAD + d4*4]) = vv;
        }
        __syncthreads();

        float s[4][4];
        #pragma unroll
        for (int i = 0; i < 4; i++)
            #pragma unroll
            for (int j = 0; j < 4; j++) s[i][j] = 0.f;

        #pragma unroll 8
        for (int d = 0; d < HD; d++) {
            float qa[4], kb2[4];
            *(float4*)qa  = *(const float4*)&sQt[d*TPAD + ty*4];
            *(float4*)kb2 = *(const float4*)&sKt[d*TPAD + tx*4];
            #pragma unroll
            for (int i = 0; i < 4; i++)
                #pragma unroll
                for (int j = 0; j < 4; j++)
                    s[i][j] = fmaf(qa[i], kb2[j], s[i][j]);
        }
        #pragma unroll
        for (int j = 0; j < 4; j++) {
            float4 p = make_float4(s[0][j]*SOFTMAX_SCALE, s[1][j]*SOFTMAX_SCALE,
                                   s[2][j]*SOFTMAX_SCALE, s[3][j]*SOFTMAX_SCALE);
            *(float4*)(&sPt[(tx*4 + j)*TPAD + ty*4]) = p;
        }
        __syncthreads();

        if (tid < 64) {
            const int r = tid;
            float tm = -INFINITY;
            #pragma unroll 8
            for (int c = 0; c < 64; c++) tm = fmaxf(tm, sPt[c*TPAD + r]);
            const float mo = rowm[r];
            const float mn = fmaxf(mo, tm);
            const float al = __expf(mo - mn);
            float sum = 0.f;
            #pragma unroll 8
            for (int c = 0; c < 64; c++) {
                float p = __expf(sPt[c*TPAD + r] - mn);
                sPt[c*TPAD + r] = p;
                sum += p;
            }
            rowl[r] = rowl[r] * al + sum;
            rowm[r] = mn;
            rowa[r] = al;
        }
        __syncthreads();

        float al_i[4];
        *(float4*)al_i = *(const float4*)&rowa[ty*4];
        #pragma unroll
        for (int i = 0; i < 4; i++)
            #pragma unroll
            for (int j = 0; j < 4; j++) acc[i][j] *= al_i[i];

        #pragma unroll 8
        for (int c = 0; c < 64; c++) {
            float p[4], vv[4];
            *(float4*)p  = *(const float4*)&sPt[c*TPAD + ty*4];
            *(float4*)vv = *(const float4*)&sV [c*TPAD + tx*4];
            #pragma unroll
            for (int i = 0; i < 4; i++)
                #pragma unroll
                for (int j = 0; j < 4; j++)
                    acc[i][j] = fmaf(p[i], vv[j], acc[i][j]);
        }
        __syncthreads();
    }

    float linv[4];
    #pragma unroll
    for (int i = 0; i < 4; i++) linv[i] = 1.f / rowl[ty*4 + i];
    #pragma unroll
    for (int i = 0; i < 4; i++) {
        float4 o = make_float4(acc[i][0]*linv[i], acc[i][1]*linv[i],
                               acc[i][2]*linv[i], acc[i][3]*linv[i]);
        *(float4*)(O + bh_off + (size_t)(qbase + ty*4 + i) * D_MODEL + tx*4) = o;
    }
}

// ==================== launch ====================
extern "C" void kernel_launch(void* const* d_in, const int* in_sizes, int n_in,
                              void* d_out, int out_size)
{
    const float* x  = (const float*)d_in[0];
    const float* Wq = (const float*)d_in[1];
    const float* Wk = (const float*)d_in[2];
    const float* Wv = (const float*)d_in[3];
    const float* Wo = (const float*)d_in[4];
    float* out = (float*)d_out;

    float *q, *k, *v, *attn, *wt;
    cudaGetSymbolAddress((void**)&q,    g_q);
    cudaGetSymbolAddress((void**)&k,    g_k);
    cudaGetSymbolAddress((void**)&v,    g_v);
    cudaGetSymbolAddress((void**)&attn, g_attn);
    cudaGetSymbolAddress((void**)&wt,   g_wt);

    cudaFuncSetAttribute(attn_kernel,
                         cudaFuncAttributeMaxDynamicSharedMemorySize, ATT_SMEM);

    const float* wtq = wt + 0 * (size_t)D_MODEL * D_MODEL;
    const float* wtk = wt + 1 * (size_t)D_MODEL * D_MODEL;
    const float* wtv = wt + 2 * (size_t)D_MODEL * D_MODEL;
    const float* wto = wt + 3 * (size_t)D_MODEL * D_MODEL;

    // 1. transpose all 4 weight matrices to N x K (K-major)
    transpose_kernel<<<dim3(32, 32, 4), dim3(32, 8)>>>(Wq, Wk, Wv, Wo, wt);

    // 2. Q/K/V projections (mma.sync tf32)
    gemm_mma_kernel<<<dim3(D_MODEL/128, MTOT/128, 3), 256>>>(
        x, wtq, wtk, wtv, q, k, v);

    // 3. attention (fp32 CUDA cores)
    attn_kernel<<<dim3(SEQ/64, NH, BATCH), 256, ATT_SMEM>>>(q, k, v, attn);

    // 4. output projection
    gemm_mma_kernel<<<dim3(D_MODEL/128, MTOT/128, 1), 256>>>(
        attn, wto, wto, wto, out, out, out);
}

// round 6
// speedup vs baseline: 3.0185x; 2.1902x over previous
#include <cuda_runtime.h>
#include <math.h>
#include <stdint.h>

#define D_MODEL 1024
#define SEQ     2048
#define BATCH   2
#define NH      16
#define HD      64
#define MTOT    (BATCH*SEQ)   // 4096

// ---------------- scratch (no allocations allowed) ----------------
__device__ float g_q[MTOT*D_MODEL];
__device__ float g_k[MTOT*D_MODEL];
__device__ float g_v[MTOT*D_MODEL];
__device__ float g_attn[MTOT*D_MODEL];
__device__ float g_wt[4*D_MODEL*D_MODEL];   // transposed weights (N x K, K-major)

extern __shared__ char dynsmem[];

// ==================== common helpers ====================
__device__ __forceinline__ uint4 tf32x4(float4 v) {
    uint4 u;
    asm("cvt.rna.tf32.f32 %0, %1;" : "=r"(u.x) : "f"(v.x));
    asm("cvt.rna.tf32.f32 %0, %1;" : "=r"(u.y) : "f"(v.y));
    asm("cvt.rna.tf32.f32 %0, %1;" : "=r"(u.z) : "f"(v.z));
    asm("cvt.rna.tf32.f32 %0, %1;" : "=r"(u.w) : "f"(v.w));
    return u;
}
__device__ __forceinline__ uint32_t tf32_1(float v) {
    uint32_t u;
    asm("cvt.rna.tf32.f32 %0, %1;" : "=r"(u) : "f"(v));
    return u;
}

#define MMA_TF32(c, a, b) \
    asm volatile("mma.sync.aligned.m16n8k8.row.col.f32.tf32.tf32.f32 " \
        "{%0,%1,%2,%3}, {%4,%5,%6,%7}, {%8,%9}, {%0,%1,%2,%3};" \
        : "+f"((c)[0]), "+f"((c)[1]), "+f"((c)[2]), "+f"((c)[3]) \
        : "r"((a)[0]), "r"((a)[1]), "r"((a)[2]), "r"((a)[3]), \
          "r"((b)[0]), "r"((b)[1]))

// ==================== mma.sync tf32 GEMM (projections) ====================
__device__ __forceinline__ int swz(int r, int c) {
    return r * 32 + ((((c >> 2) ^ r) & 7) << 2) + (c & 3);
}

__global__ __launch_bounds__(256, 1) void gemm_mma_kernel(
    const float* __restrict__ A,
    const float* __restrict__ B0, const float* __restrict__ B1, const float* __restrict__ B2,
    float* __restrict__ C0, float* __restrict__ C1, float* __restrict__ C2)
{
    __shared__ float sA[128 * 32];
    __shared__ float sB[128 * 32];

    const int tid    = threadIdx.x;
    const int wid    = tid >> 5;
    const int lane   = tid & 31;
    const int warp_m = wid & 1;
    const int warp_n = wid >> 1;
    const int g      = lane >> 2;
    const int tg     = lane & 3;

    const int z = blockIdx.z;
    const float* __restrict__ B = (z == 0) ? B0 : ((z == 1) ? B1 : B2);
    float* __restrict__ C       = (z == 0) ? C0 : ((z == 1) ? C1 : C2);
    const int colbase = blockIdx.x * 128;
    const int rowbase = blockIdx.y * 128;

    float acc[4][4][4];
    #pragma unroll
    for (int mi = 0; mi < 4; mi++)
        #pragma unroll
        for (int ni = 0; ni < 4; ni++)
            #pragma unroll
            for (int q = 0; q < 4; q++) acc[mi][ni][q] = 0.f;

    float4 pa[4], pb[4];
    #pragma unroll
    for (int l = 0; l < 4; l++) {
        int e = tid + l * 256;
        int r = e >> 3, c4 = e & 7;
        pa[l] = *(const float4*)(A + (size_t)(rowbase + r) * D_MODEL + c4 * 4);
        pb[l] = *(const float4*)(B + (size_t)(colbase + r) * D_MODEL + c4 * 4);
    }

    const int NK = D_MODEL / 32;
    for (int kt = 0; kt < NK; kt++) {
        __syncthreads();
        #pragma unroll
        for (int l = 0; l < 4; l++) {
            int e = tid + l * 256;
            int r = e >> 3, c4 = e & 7;
            *(uint4*)&sA[swz(r, c4 * 4)] = tf32x4(pa[l]);
            *(uint4*)&sB[swz(r, c4 * 4)] = tf32x4(pb[l]);
        }
        __syncthreads();

        if (kt < NK - 1) {
            const float* An = A + (kt + 1) * 32;
            const float* Bn = B + (kt + 1) * 32;
            #pragma unroll
            for (int l = 0; l < 4; l++) {
                int e = tid + l * 256;
                int r = e >> 3, c4 = e & 7;
                pa[l] = *(const float4*)(An + (size_t)(rowbase + r) * D_MODEL + c4 * 4);
                pb[l] = *(const float4*)(Bn + (size_t)(colbase + r) * D_MODEL + c4 * 4);
            }
        }

        #pragma unroll
        for (int kk = 0; kk < 4; kk++) {
            uint32_t af[4][4], bf[4][2];
            const int col = kk * 8 + tg;
            #pragma unroll
            for (int mi = 0; mi < 4; mi++) {
                int row = warp_m * 64 + mi * 16 + g;
                af[mi][0] = __float_as_uint(sA[swz(row,     col)]);
                af[mi][1] = __float_as_uint(sA[swz(row + 8, col)]);
                af[mi][2] = __float_as_uint(sA[swz(row,     col + 4)]);
                af[mi][3] = __float_as_uint(sA[swz(row + 8, col + 4)]);
            }
            #pragma unroll
            for (int ni = 0; ni < 4; ni++) {
                int n = warp_n * 32 + ni * 8 + g;
                bf[ni][0] = __float_as_uint(sB[swz(n, col)]);
                bf[ni][1] = __float_as_uint(sB[swz(n, col + 4)]);
            }
            #pragma unroll
            for (int mi = 0; mi < 4; mi++)
                #pragma unroll
                for (int ni = 0; ni < 4; ni++)
                    MMA_TF32(acc[mi][ni], af[mi], bf[ni]);
        }
    }

    #pragma unroll
    for (int mi = 0; mi < 4; mi++) {
        int row = rowbase + warp_m * 64 + mi * 16 + g;
        #pragma unroll
        for (int ni = 0; ni < 4; ni++) {
            int col = colbase + warp_n * 32 + ni * 8 + tg * 2;
            *(float2*)(C + (size_t)row * D_MODEL + col) =
                make_float2(acc[mi][ni][0], acc[mi][ni][1]);
            *(float2*)(C + (size_t)(row + 8) * D_MODEL + col) =
                make_float2(acc[mi][ni][2], acc[mi][ni][3]);
        }
    }
}

// ==================== weight transpose ====================
__global__ __launch_bounds__(256) void transpose_kernel(
    const float* __restrict__ s0, const float* __restrict__ s1,
    const float* __restrict__ s2, const float* __restrict__ s3,
    float* __restrict__ dst)
{
    __shared__ float ts[32][33];
    const int z = blockIdx.z;
    const float* src = (z == 0) ? s0 : (z == 1) ? s1 : (z == 2) ? s2 : s3;
    float* d = dst + (size_t)z * D_MODEL * D_MODEL;
    int x = blockIdx.x * 32 + threadIdx.x;
    int y = blockIdx.y * 32 + threadIdx.y;
    #pragma unroll
    for (int j = 0; j < 32; j += 8)
        ts[threadIdx.y + j][threadIdx.x] = src[(size_t)(y + j) * D_MODEL + x];
    __syncthreads();
    int x2 = blockIdx.y * 32 + threadIdx.x;
    int y2 = blockIdx.x * 32 + threadIdx.y;
    #pragma unroll
    for (int j = 0; j < 32; j += 8)
        d[(size_t)(y2 + j) * D_MODEL + x2] = ts[threadIdx.x][threadIdx.y + j];
}

// ==================== Flash attention v2, mma.sync tf32 ====================
// CTA: 128 q-rows of one (b,h). 8 warps, warp w owns rows [16w, 16w+16).
// K-tile: 64 cols. S = Q Kt per warp: 1m x 8n x 8k mma. Softmax on fragments.
// P->A-fragment via quad shuffles. PV: 8n(hd) x 8k mma, fp32 acc.
#define QW 68
#define KW 68
#define VW 72
#define SQ_OFF 0
#define SK_OFF (128*QW)
#define SV_OFF (SK_OFF + 64*KW)
#define ATT_SMEM ((SV_OFF + 64*VW) * (int)sizeof(float))   // ~70.7 KB
#define SM_SC 0.18033688f   // 0.125 * log2(e)

__global__ __launch_bounds__(256, 1) void attn_mma_kernel(
    const float* __restrict__ Qg, const float* __restrict__ Kg,
    const float* __restrict__ Vg, float* __restrict__ Og)
{
    uint32_t* sm = (uint32_t*)dynsmem;
    uint32_t* sQ = sm + SQ_OFF;
    uint32_t* sK = sm + SK_OFF;
    uint32_t* sV = sm + SV_OFF;

    const int tid  = threadIdx.x;
    const int wid  = tid >> 5;
    const int lane = tid & 31;
    const int g    = lane >> 2;
    const int tg   = lane & 3;
    const int wb   = wid * 16;          // warp row base

    const int b = blockIdx.z, h = blockIdx.y;
    const int qbase = blockIdx.x * 128;
    const size_t bh_off = ((size_t)b * SEQ) * D_MODEL + (size_t)h * HD;

    // load Q tile (128 x 64) as tf32
    #pragma unroll
    for (int l = 0; l < 8; l++) {
        int e  = tid + l * 256;         // 0..2047
        int r  = e >> 4;                // 0..127
        int c4 = e & 15;                // 0..15
        float4 v = *(const float4*)(Qg + bh_off + (size_t)(qbase + r) * D_MODEL + c4 * 4);
        *(uint4*)&sQ[r * QW + c4 * 4] = tf32x4(v);
    }

    float o[8][4];
    #pragma unroll
    for (int nt = 0; nt < 8; nt++)
        #pragma unroll
        for (int q = 0; q < 4; q++) o[nt][q] = 0.f;
    float m0 = -INFINITY, m1 = -INFINITY, l0 = 0.f, l1 = 0.f;

    for (int kt = 0; kt < SEQ / 64; kt++) {
        __syncthreads();
        // load K,V tiles (64 x 64) as tf32
        #pragma unroll
        for (int l = 0; l < 4; l++) {
            int e  = tid + l * 256;     // 0..1023
            int r  = e >> 4;            // 0..63
            int c4 = e & 15;
            float4 kv = *(const float4*)(Kg + bh_off + (size_t)(kt * 64 + r) * D_MODEL + c4 * 4);
            *(uint4*)&sK[r * KW + c4 * 4] = tf32x4(kv);
            float4 vv = *(const float4*)(Vg + bh_off + (size_t)(kt * 64 + r) * D_MODEL + c4 * 4);
            *(uint4*)&sV[r * VW + c4 * 4] = tf32x4(vv);
        }
        __syncthreads();

        // S = Q Kt  (warp: m16 x n64, k64)
        float s[8][4];
        #pragma unroll
        for (int nt = 0; nt < 8; nt++)
            #pragma unroll
            for (int q = 0; q < 4; q++) s[nt][q] = 0.f;

        #pragma unroll
        for (int kk = 0; kk < 8; kk++) {
            uint32_t af[4];
            const int col = kk * 8 + tg;
            af[0] = sQ[(wb + g    ) * QW + col];
            af[1] = sQ[(wb + g + 8) * QW + col];
            af[2] = sQ[(wb + g    ) * QW + col + 4];
            af[3] = sQ[(wb + g + 8) * QW + col + 4];
            #pragma unroll
            for (int nt = 0; nt < 8; nt++) {
                uint32_t bf[2];
                bf[0] = sK[(nt * 8 + g) * KW + col];
                bf[1] = sK[(nt * 8 + g) * KW + col + 4];
                MMA_TF32(s[nt], af, bf);
            }
        }

        // online softmax (rows g and g+8, stats replicated in quad)
        float tm0 = -INFINITY, tm1 = -INFINITY;
        #pragma unroll
        for (int nt = 0; nt < 8; nt++) {
            tm0 = fmaxf(tm0, fmaxf(s[nt][0], s[nt][1]));
            tm1 = fmaxf(tm1, fmaxf(s[nt][2], s[nt][3]));
        }
        tm0 = fmaxf(tm0, __shfl_xor_sync(0xffffffff, tm0, 1));
        tm0 = fmaxf(tm0, __shfl_xor_sync(0xffffffff, tm0, 2));
        tm1 = fmaxf(tm1, __shfl_xor_sync(0xffffffff, tm1, 1));
        tm1 = fmaxf(tm1, __shfl_xor_sync(0xffffffff, tm1, 2));

        const float mn0 = fmaxf(m0, tm0);
        const float mn1 = fmaxf(m1, tm1);
        const float al0 = exp2f((m0 - mn0) * SM_SC);
        const float al1 = exp2f((m1 - mn1) * SM_SC);
        m0 = mn0; m1 = mn1;

        float sum0 = 0.f, sum1 = 0.f;
        #pragma unroll
        for (int nt = 0; nt < 8; nt++) {
            s[nt][0] = exp2f((s[nt][0] - mn0) * SM_SC);
            s[nt][1] = exp2f((s[nt][1] - mn0) * SM_SC);
            s[nt][2] = exp2f((s[nt][2] - mn1) * SM_SC);
            s[nt][3] = exp2f((s[nt][3] - mn1) * SM_SC);
            sum0 += s[nt][0] + s[nt][1];
            sum1 += s[nt][2] + s[nt][3];
        }
        sum0 += __shfl_xor_sync(0xffffffff, sum0, 1);
        sum0 += __shfl_xor_sync(0xffffffff, sum0, 2);
        sum1 += __shfl_xor_sync(0xffffffff, sum1, 1);
        sum1 += __shfl_xor_sync(0xffffffff, sum1, 2);
        l0 = l0 * al0 + sum0;
        l1 = l1 * al1 + sum1;

        #pragma unroll
        for (int nt = 0; nt < 8; nt++) {
            o[nt][0] *= al0; o[nt][1] *= al0;
            o[nt][2] *= al1; o[nt][3] *= al1;
        }

        // O += P V   (P fragments via quad shuffles)
        const int src0 = (lane & ~3) | (tg >> 1);
        const int src1 = src0 + 2;
        const bool odd = tg & 1;
        #pragma unroll
        for (int kk = 0; kk < 8; kk++) {
            float x0 = __shfl_sync(0xffffffff, s[kk][0], src0);
            float x1 = __shfl_sync(0xffffffff, s[kk][1], src0);
            float y0 = __shfl_sync(0xffffffff, s[kk][2], src0);
            float y1 = __shfl_sync(0xffffffff, s[kk][3], src0);
            float w0 = __shfl_sync(0xffffffff, s[kk][0], src1);
            float w1 = __shfl_sync(0xffffffff, s[kk][1], src1);
            float u0 = __shfl_sync(0xffffffff, s[kk][2], src1);
            float u1 = __shfl_sync(0xffffffff, s[kk][3], src1);
            uint32_t af[4];
            af[0] = tf32_1(odd ? x1 : x0);   // (row g,   col kk*8+tg)
            af[1] = tf32_1(odd ? y1 : y0);   // (row g+8, col kk*8+tg)
            af[2] = tf32_1(odd ? w1 : w0);   // (row g,   col kk*8+tg+4)
            af[3] = tf32_1(odd ? u1 : u0);   // (row g+8, col kk*8+tg+4)
            #pragma unroll
            for (int nt = 0; nt < 8; nt++) {
                uint32_t bf[2];
                bf[0] = sV[(kk * 8 + tg    ) * VW + nt * 8 + g];
                bf[1] = sV[(kk * 8 + tg + 4) * VW + nt * 8 + g];
                MMA_TF32(o[nt], af, bf);
            }
        }
    }

    // normalize + store
    const float li0 = 1.f / l0, li1 = 1.f / l1;
    const int row0 = qbase + wb + g;
    #pragma unroll
    for (int nt = 0; nt < 8; nt++) {
        int col = nt * 8 + tg * 2;
        *(float2*)(Og + bh_off + (size_t)row0 * D_MODEL + col) =
            make_float2(o[nt][0] * li0, o[nt][1] * li0);
        *(float2*)(Og + bh_off + (size_t)(row0 + 8) * D_MODEL + col) =
            make_float2(o[nt][2] * li1, o[nt][3] * li1);
    }
}

// ==================== launch ====================
extern "C" void kernel_launch(void* const* d_in, const int* in_sizes, int n_in,
                              void* d_out, int out_size)
{
    const float* x  = (const float*)d_in[0];
    const float* Wq = (const float*)d_in[1];
    const float* Wk = (const float*)d_in[2];
    const float* Wv = (const float*)d_in[3];
    const float* Wo = (const float*)d_in[4];
    float* out = (float*)d_out;

    float *q, *k, *v, *attn, *wt;
    cudaGetSymbolAddress((void**)&q,    g_q);
    cudaGetSymbolAddress((void**)&k,    g_k);
    cudaGetSymbolAddress((void**)&v,    g_v);
    cudaGetSymbolAddress((void**)&attn, g_attn);
    cudaGetSymbolAddress((void**)&wt,   g_wt);

    cudaFuncSetAttribute(attn_mma_kernel,
                         cudaFuncAttributeMaxDynamicSharedMemorySize, ATT_SMEM);

    const float* wtq = wt + 0 * (size_t)D_MODEL * D_MODEL;
    const float* wtk = wt + 1 * (size_t)D_MODEL * D_MODEL;
    const float* wtv = wt + 2 * (size_t)D_MODEL * D_MODEL;
    const float* wto = wt + 3 * (size_t)D_MODEL * D_MODEL;

    transpose_kernel<<<dim3(32, 32, 4), dim3(32, 8)>>>(Wq, Wk, Wv, Wo, wt);

    gemm_mma_kernel<<<dim3(D_MODEL/128, MTOT/128, 3), 256>>>(
        x, wtq, wtk, wtv, q, k, v);

    attn_mma_kernel<<<dim3(SEQ/128, NH, BATCH), 256, ATT_SMEM>>>(q, k, v, attn);

    gemm_mma_kernel<<<dim3(D_MODEL/128, MTOT/128, 1), 256>>>(
        attn, wto, wto, wto, out, out, out);
}

// round 7
// speedup vs baseline: 3.8728x; 1.2830x over previous
#include <cuda_runtime.h>
#include <math.h>
#include <stdint.h>

#define D_MODEL 1024
#define SEQ     2048
#define BATCH   2
#define NH      16
#define HD      64
#define MTOT    (BATCH*SEQ)   // 4096

// ---------------- scratch (no allocations allowed) ----------------
__device__ float g_x[MTOT*D_MODEL];         // tf32-rounded copy of x
__device__ float g_q[MTOT*D_MODEL];
__device__ float g_k[MTOT*D_MODEL];
__device__ float g_v[MTOT*D_MODEL];
__device__ float g_attn[MTOT*D_MODEL];
__device__ float g_wt[4*D_MODEL*D_MODEL];   // transposed+rounded weights (N x K)

extern __shared__ char dynsmem[];

// ==================== helpers ====================
__device__ __forceinline__ uint32_t smem_to_u32(const void* p) {
    uint32_t a;
    asm("{ .reg .u64 t; cvta.to.shared.u64 t, %1; cvt.u32.u64 %0, t; }" : "=r"(a) : "l"(p));
    return a;
}
__device__ __forceinline__ uint32_t tf32_1(float v) {
    uint32_t u;
    asm("cvt.rna.tf32.f32 %0, %1;" : "=r"(u) : "f"(v));
    return u;
}
__device__ __forceinline__ float roundtf(float v) { return __uint_as_float(tf32_1(v)); }

#define MMA_TF32(c, a, b) \
    asm volatile("mma.sync.aligned.m16n8k8.row.col.f32.tf32.tf32.f32 " \
        "{%0,%1,%2,%3}, {%4,%5,%6,%7}, {%8,%9}, {%0,%1,%2,%3};" \
        : "+f"((c)[0]), "+f"((c)[1]), "+f"((c)[2]), "+f"((c)[3]) \
        : "r"((a)[0]), "r"((a)[1]), "r"((a)[2]), "r"((a)[3]), \
          "r"((b)[0]), "r"((b)[1]))

#define CP16(dst, src) \
    asm volatile("cp.async.cg.shared.global [%0], [%1], 16;" :: "r"(dst), "l"(src))
#define CP_COMMIT() asm volatile("cp.async.commit_group;")
#define CP_WAIT(N)  asm volatile("cp.async.wait_group " #N ";")

__device__ __forceinline__ int swz(int r, int c) {
    return r * 32 + ((((c >> 2) ^ r) & 7) << 2) + (c & 3);
}

// ==================== tf32 GEMM, cp.async 3-stage ====================
// C[M,N] = A[M,K] @ Bt[N,K]^T. Inputs pre-rounded to tf32 in gmem.
#define GS 3
#define G_SMEM (GS * 32768)

__global__ __launch_bounds__(256, 2) void gemm_mma_kernel(
    const float* __restrict__ A,
    const float* __restrict__ B0, const float* __restrict__ B1, const float* __restrict__ B2,
    float* __restrict__ C0, float* __restrict__ C1, float* __restrict__ C2,
    int round_out)
{
    float* smem = (float*)dynsmem;
    const uint32_t sbase = smem_to_u32(smem);

    const int tid    = threadIdx.x;
    const int wid    = tid >> 5;
    const int lane   = tid & 31;
    const int warp_m = wid & 1;
    const int warp_n = wid >> 1;
    const int g      = lane >> 2;
    const int tg     = lane & 3;

    const int z = blockIdx.z;
    const float* __restrict__ B = (z == 0) ? B0 : ((z == 1) ? B1 : B2);
    float* __restrict__ C       = (z == 0) ? C0 : ((z == 1) ? C1 : C2);
    const int colbase = blockIdx.x * 128;
    const int rowbase = blockIdx.y * 128;

    // per-thread load coords
    const int lr = tid >> 3;            // 0..31 (row step 32 over 4 iters)
    const int lc = (tid & 7) * 4;       // col in k-tile

    float acc[4][4][4];
    #pragma unroll
    for (int mi = 0; mi < 4; mi++)
        #pragma unroll
        for (int ni = 0; ni < 4; ni++)
            #pragma unroll
            for (int q = 0; q < 4; q++) acc[mi][ni][q] = 0.f;

    const int NK = D_MODEL / 32;

    // prologue: stages 0..GS-2
    #pragma unroll
    for (int s = 0; s < GS - 1; s++) {
        #pragma unroll
        for (int l = 0; l < 4; l++) {
            int r = lr + l * 32;
            uint32_t off = (uint32_t)(s * 8192 + swz(r, lc)) * 4;
            CP16(sbase + off,         A + (size_t)(rowbase + r) * D_MODEL + s * 32 + lc);
            CP16(sbase + off + 16384, B + (size_t)(colbase + r) * D_MODEL + s * 32 + lc);
        }
        CP_COMMIT();
    }

    for (int kt = 0; kt < NK; kt++) {
        __syncthreads();                    // all warps done reading stage (kt-1)%GS
        const int nk = kt + GS - 1;
        if (nk < NK) {
            const int s = nk % GS;
            #pragma unroll
            for (int l = 0; l < 4; l++) {
                int r = lr + l * 32;
                uint32_t off = (uint32_t)(s * 8192 + swz(r, lc)) * 4;
                CP16(sbase + off,         A + (size_t)(rowbase + r) * D_MODEL + nk * 32 + lc);
                CP16(sbase + off + 16384, B + (size_t)(colbase + r) * D_MODEL + nk * 32 + lc);
            }
        }
        CP_COMMIT();
        CP_WAIT(2);                         // stage kt ready
        __syncthreads();

        const float* sA = smem + (kt % GS) * 8192;
        const float* sB = sA + 4096;

        #pragma unroll
        for (int kk = 0; kk < 4; kk++) {
            uint32_t af[4][4], bf[4][2];
            const int col = kk * 8 + tg;
            #pragma unroll
            for (int mi = 0; mi < 4; mi++) {
                int row = warp_m * 64 + mi * 16 + g;
                af[mi][0] = __float_as_uint(sA[swz(row,     col)]);
                af[mi][1] = __float_as_uint(sA[swz(row + 8, col)]);
                af[mi][2] = __float_as_uint(sA[swz(row,     col + 4)]);
                af[mi][3] = __float_as_uint(sA[swz(row + 8, col + 4)]);
            }
            #pragma unroll
            for (int ni = 0; ni < 4; ni++) {
                int n = warp_n * 32 + ni * 8 + g;
                bf[ni][0] = __float_as_uint(sB[swz(n, col)]);
                bf[ni][1] = __float_as_uint(sB[swz(n, col + 4)]);
            }
            #pragma unroll
            for (int mi = 0; mi < 4; mi++)
                #pragma unroll
                for (int ni = 0; ni < 4; ni++)
                    MMA_TF32(acc[mi][ni], af[mi], bf[ni]);
        }
    }

    #pragma unroll
    for (int mi = 0; mi < 4; mi++) {
        int row = rowbase + warp_m * 64 + mi * 16 + g;
        #pragma unroll
        for (int ni = 0; ni < 4; ni++) {
            int col = colbase + warp_n * 32 + ni * 8 + tg * 2;
            float v0 = acc[mi][ni][0], v1 = acc[mi][ni][1];
            float v2 = acc[mi][ni][2], v3 = acc[mi][ni][3];
            if (round_out) {
                v0 = roundtf(v0); v1 = roundtf(v1);
                v2 = roundtf(v2); v3 = roundtf(v3);
            }
            *(float2*)(C + (size_t)row * D_MODEL + col)       = make_float2(v0, v1);
            *(float2*)(C + (size_t)(row + 8) * D_MODEL + col) = make_float2(v2, v3);
        }
    }
}

// ==================== prep kernels ====================
__global__ __launch_bounds__(256) void round_kernel(
    const float* __restrict__ src, float* __restrict__ dst)
{
    int i = blockIdx.x * 256 + threadIdx.x;
    float4 v = ((const float4*)src)[i];
    v.x = roundtf(v.x); v.y = roundtf(v.y); v.z = roundtf(v.z); v.w = roundtf(v.w);
    ((float4*)dst)[i] = v;
}

__global__ __launch_bounds__(256) void transpose_kernel(
    const float* __restrict__ s0, const float* __restrict__ s1,
    const float* __restrict__ s2, const float* __restrict__ s3,
    float* __restrict__ dst)
{
    __shared__ float ts[32][33];
    const int z = blockIdx.z;
    const float* src = (z == 0) ? s0 : (z == 1) ? s1 : (z == 2) ? s2 : s3;
    float* d = dst + (size_t)z * D_MODEL * D_MODEL;
    int x = blockIdx.x * 32 + threadIdx.x;
    int y = blockIdx.y * 32 + threadIdx.y;
    #pragma unroll
    for (int j = 0; j < 32; j += 8)
        ts[threadIdx.y + j][threadIdx.x] = src[(size_t)(y + j) * D_MODEL + x];
    __syncthreads();
    int x2 = blockIdx.y * 32 + threadIdx.x;
    int y2 = blockIdx.x * 32 + threadIdx.y;
    #pragma unroll
    for (int j = 0; j < 32; j += 8)
        d[(size_t)(y2 + j) * D_MODEL + x2] = roundtf(ts[threadIdx.x][threadIdx.y + j]);
}

// ==================== Flash attention v2, tf32 mma + cp.async ====================
// Q: 128x64 (QW=68). K,V: 64x64 double-buffered (KW=68, VW=72). All pre-rounded fp32.
#define QW 68
#define KW 68
#define VW 72
#define SK_OFF 8704                       // 128*QW
#define SV_OFF (SK_OFF + 2*64*KW)         // 17408
#define ATT_WORDS (SV_OFF + 2*64*VW)      // 26624
#define ATT_SMEM (ATT_WORDS * 4)          // 106496
#define SM_SC 0.18033688f                 // 0.125 * log2(e)

__global__ __launch_bounds__(256, 1) void attn_mma_kernel(
    const float* __restrict__ Qg, const float* __restrict__ Kg,
    const float* __restrict__ Vg, float* __restrict__ Og)
{
    float* sm = (float*)dynsmem;
    const uint32_t sbase = smem_to_u32(sm);

    const int tid  = threadIdx.x;
    const int wid  = tid >> 5;
    const int lane = tid & 31;
    const int g    = lane >> 2;
    const int tg   = lane & 3;
    const int wb   = wid * 16;

    const int b = blockIdx.z, h = blockIdx.y;
    const int qbase = blockIdx.x * 128;
    const size_t bh_off = ((size_t)b * SEQ) * D_MODEL + (size_t)h * HD;

    const int kr = tid >> 4;              // 0..15 (row step 16 over 4 iters)
    const int kc = (tid & 15) * 4;        // 0..60

    // group 0: Q tile + K/V tile 0
    #pragma unroll
    for (int l = 0; l < 8; l++) {
        int r = kr + l * 16;              // 0..127
        CP16(sbase + (uint32_t)(r * QW + kc) * 4,
             Qg + bh_off + (size_t)(qbase + r) * D_MODEL + kc);
    }
    #pragma unroll
    for (int l = 0; l < 4; l++) {
        int r = kr + l * 16;              // 0..63
        CP16(sbase + (uint32_t)(SK_OFF + r * KW + kc) * 4,
             Kg + bh_off + (size_t)r * D_MODEL + kc);
        CP16(sbase + (uint32_t)(SV_OFF + r * VW + kc) * 4,
             Vg + bh_off + (size_t)r * D_MODEL + kc);
    }
    CP_COMMIT();

    float o[8][4];
    #pragma unroll
    for (int nt = 0; nt < 8; nt++)
        #pragma unroll
        for (int q = 0; q < 4; q++) o[nt][q] = 0.f;
    float m0 = -INFINITY, m1 = -INFINITY, l0 = 0.f, l1 = 0.f;

    const int NT = SEQ / 64;
    for (int kt = 0; kt < NT; kt++) {
        const int bsel = kt & 1;
        __syncthreads();                  // prev tile fully consumed
        if (kt + 1 < NT) {
            const int nb = 1 - bsel;
            #pragma unroll
            for (int l = 0; l < 4; l++) {
                int r = kr + l * 16;
                CP16(sbase + (uint32_t)(SK_OFF + nb * 64 * KW + r * KW + kc) * 4,
                     Kg + bh_off + (size_t)((kt + 1) * 64 + r) * D_MODEL + kc);
                CP16(sbase + (uint32_t)(SV_OFF + nb * 64 * VW + r * VW + kc) * 4,
                     Vg + bh_off + (size_t)((kt + 1) * 64 + r) * D_MODEL + kc);
            }
        }
        CP_COMMIT();
        CP_WAIT(1);
        __syncthreads();

        const float* sQ = sm;
        const float* sK = sm + SK_OFF + bsel * 64 * KW;
        const float* sV = sm + SV_OFF + bsel * 64 * VW;

        // S = Q Kt
        float s[8][4];
        #pragma unroll
        for (int nt = 0; nt < 8; nt++)
            #pragma unroll
            for (int q = 0; q < 4; q++) s[nt][q] = 0.f;

        #pragma unroll
        for (int kk = 0; kk < 8; kk++) {
            uint32_t af[4];
            const int col = kk * 8 + tg;
            af[0] = __float_as_uint(sQ[(wb + g    ) * QW + col]);
            af[1] = __float_as_uint(sQ[(wb + g + 8) * QW + col]);
            af[2] = __float_as_uint(sQ[(wb + g    ) * QW + col + 4]);
            af[3] = __float_as_uint(sQ[(wb + g + 8) * QW + col + 4]);
            #pragma unroll
            for (int nt = 0; nt < 8; nt++) {
                uint32_t bf[2];
                bf[0] = __float_as_uint(sK[(nt * 8 + g) * KW + col]);
                bf[1] = __float_as_uint(sK[(nt * 8 + g) * KW + col + 4]);
                MMA_TF32(s[nt], af, bf);
            }
        }

        // online softmax
        float tm0 = -INFINITY, tm1 = -INFINITY;
        #pragma unroll
        for (int nt = 0; nt < 8; nt++) {
            tm0 = fmaxf(tm0, fmaxf(s[nt][0], s[nt][1]));
            tm1 = fmaxf(tm1, fmaxf(s[nt][2], s[nt][3]));
        }
        tm0 = fmaxf(tm0, __shfl_xor_sync(0xffffffff, tm0, 1));
        tm0 = fmaxf(tm0, __shfl_xor_sync(0xffffffff, tm0, 2));
        tm1 = fmaxf(tm1, __shfl_xor_sync(0xffffffff, tm1, 1));
        tm1 = fmaxf(tm1, __shfl_xor_sync(0xffffffff, tm1, 2));

        const float mn0 = fmaxf(m0, tm0);
        const float mn1 = fmaxf(m1, tm1);
        const float al0 = exp2f((m0 - mn0) * SM_SC);
        const float al1 = exp2f((m1 - mn1) * SM_SC);
        m0 = mn0; m1 = mn1;

        float sum0 = 0.f, sum1 = 0.f;
        #pragma unroll
        for (int nt = 0; nt < 8; nt++) {
            s[nt][0] = exp2f((s[nt][0] - mn0) * SM_SC);
            s[nt][1] = exp2f((s[nt][1] - mn0) * SM_SC);
            s[nt][2] = exp2f((s[nt][2] - mn1) * SM_SC);
            s[nt][3] = exp2f((s[nt][3] - mn1) * SM_SC);
            sum0 += s[nt][0] + s[nt][1];
            sum1 += s[nt][2] + s[nt][3];
        }
        sum0 += __shfl_xor_sync(0xffffffff, sum0, 1);
        sum0 += __shfl_xor_sync(0xffffffff, sum0, 2);
        sum1 += __shfl_xor_sync(0xffffffff, sum1, 1);
        sum1 += __shfl_xor_sync(0xffffffff, sum1, 2);
        l0 = l0 * al0 + sum0;
        l1 = l1 * al1 + sum1;

        #pragma unroll
        for (int nt = 0; nt < 8; nt++) {
            o[nt][0] *= al0; o[nt][1] *= al0;
            o[nt][2] *= al1; o[nt][3] *= al1;
        }

        // O += P V  (P C-frag -> A-frag via quad shuffles)
        const int src0 = (lane & ~3) | (tg >> 1);
        const int src1 = src0 + 2;
        const bool odd = tg & 1;
        #pragma unroll
        for (int kk = 0; kk < 8; kk++) {
            float x0 = __shfl_sync(0xffffffff, s[kk][0], src0);
            float x1 = __shfl_sync(0xffffffff, s[kk][1], src0);
            float y0 = __shfl_sync(0xffffffff, s[kk][2], src0);
            float y1 = __shfl_sync(0xffffffff, s[kk][3], src0);
            float w0 = __shfl_sync(0xffffffff, s[kk][0], src1);
            float w1 = __shfl_sync(0xffffffff, s[kk][1], src1);
            float u0 = __shfl_sync(0xffffffff, s[kk][2], src1);
            float u1 = __shfl_sync(0xffffffff, s[kk][3], src1);
            uint32_t af[4];
            af[0] = tf32_1(odd ? x1 : x0);
            af[1] = tf32_1(odd ? y1 : y0);
            af[2] = tf32_1(odd ? w1 : w0);
            af[3] = tf32_1(odd ? u1 : u0);
            #pragma unroll
            for (int nt = 0; nt < 8; nt++) {
                uint32_t bf[2];
                bf[0] = __float_as_uint(sV[(kk * 8 + tg    ) * VW + nt * 8 + g]);
                bf[1] = __float_as_uint(sV[(kk * 8 + tg + 4) * VW + nt * 8 + g]);
                MMA_TF32(o[nt], af, bf);
            }
        }
    }

    // normalize, round (consumer is Wo mma), store
    const float li0 = 1.f / l0, li1 = 1.f / l1;
    const int row0 = qbase + wb + g;
    #pragma unroll
    for (int nt = 0; nt < 8; nt++) {
        int col = nt * 8 + tg * 2;
        *(float2*)(Og + bh_off + (size_t)row0 * D_MODEL + col) =
            make_float2(roundtf(o[nt][0] * li0), roundtf(o[nt][1] * li0));
        *(float2*)(Og + bh_off + (size_t)(row0 + 8) * D_MODEL + col) =
            make_float2(roundtf(o[nt][2] * li1), roundtf(o[nt][3] * li1));
    }
}

// ==================== launch ====================
extern "C" void kernel_launch(void* const* d_in, const int* in_sizes, int n_in,
                              void* d_out, int out_size)
{
    const float* x  = (const float*)d_in[0];
    const float* Wq = (const float*)d_in[1];
    const float* Wk = (const float*)d_in[2];
    const float* Wv = (const float*)d_in[3];
    const float* Wo = (const float*)d_in[4];
    float* out = (float*)d_out;

    float *xr, *q, *k, *v, *attn, *wt;
    cudaGetSymbolAddress((void**)&xr,   g_x);
    cudaGetSymbolAddress((void**)&q,    g_q);
    cudaGetSymbolAddress((void**)&k,    g_k);
    cudaGetSymbolAddress((void**)&v,    g_v);
    cudaGetSymbolAddress((void**)&attn, g_attn);
    cudaGetSymbolAddress((void**)&wt,   g_wt);

    cudaFuncSetAttribute(attn_mma_kernel,
                         cudaFuncAttributeMaxDynamicSharedMemorySize, ATT_SMEM);
    cudaFuncSetAttribute(gemm_mma_kernel,
                         cudaFuncAttributeMaxDynamicSharedMemorySize, G_SMEM);

    const float* wtq = wt + 0 * (size_t)D_MODEL * D_MODEL;
    const float* wtk = wt + 1 * (size_t)D_MODEL * D_MODEL;
    const float* wtv = wt + 2 * (size_t)D_MODEL * D_MODEL;
    const float* wto = wt + 3 * (size_t)D_MODEL * D_MODEL;

    round_kernel<<<MTOT * D_MODEL / 1024, 256>>>(x, xr);
    transpose_kernel<<<dim3(32, 32, 4), dim3(32, 8)>>>(Wq, Wk, Wv, Wo, wt);

    gemm_mma_kernel<<<dim3(D_MODEL/128, MTOT/128, 3), 256, G_SMEM>>>(
        xr, wtq, wtk, wtv, q, k, v, 1);

    attn_mma_kernel<<<dim3(SEQ/128, NH, BATCH), 256, ATT_SMEM>>>(q, k, v, attn);

    gemm_mma_kernel<<<dim3(D_MODEL/128, MTOT/128, 1), 256, G_SMEM>>>(
        attn, wto, wto, wto, out, out, out, 0);
}